// round 12
// baseline (speedup 1.0000x reference)
#include <cuda_runtime.h>
#include <cuda_fp16.h>
#include <cstdint>

#define NU 100000
#define NT 100000
#define NN 200000
#define NE 600000
#define NSLOT (2 * NN)
#define NPAD (NN + 192)          // row padding: tail CTAs may read past M

// ---- scratch (device globals; no runtime allocation) ----
// activations: single fp16 plane (rounded once per layer)
__device__ __align__(16) __half g_X1[(size_t)NPAD * 128];
__device__ __align__(16) __half g_X2[(size_t)NPAD * 128];
__device__ __align__(16) __half g_agg[(size_t)(NSLOT + 192) * 128];
// CSR structures
__device__ int g_cnt[NSLOT];
__device__ int g_off[NSLOT];
__device__ int g_cur[NSLOT];
__device__ int g_bsum[1024];
__device__ int g_esrc[NE];
// pre-converted weights, fp16 hi/lo planes, [N=128, Ktot] K-major rows:
// featU @0 (Ktot128), featT @16384, lin @32768, conv @49152 (Ktot384), o1 @98304
#define BTOT 114688
__device__ __align__(16) __half g_Wh[BTOT];
__device__ __align__(16) __half g_Wl[BTOT];
__device__ float g_biasU[128];

__device__ __forceinline__ float lrelu(float x) { return x > 0.f ? x : 0.01f * x; }

// ======================= PTX helpers (portable sm_80+) =======================
__device__ __forceinline__ uint32_t smem_to_u32(const void* p) {
    uint32_t a;
    asm("{ .reg .u64 t; cvta.to.shared.u64 t, %1; cvt.u32.u64 %0, t; }" : "=r"(a) : "l"(p));
    return a;
}
__device__ __forceinline__ void ldsm_x4(uint32_t& r0, uint32_t& r1, uint32_t& r2,
                                        uint32_t& r3, uint32_t a) {
    asm volatile("ldmatrix.sync.aligned.m8n8.x4.shared.b16 {%0,%1,%2,%3}, [%4];"
                 : "=r"(r0), "=r"(r1), "=r"(r2), "=r"(r3) : "r"(a));
}
__device__ __forceinline__ void mma16816(float* d, uint32_t a0, uint32_t a1, uint32_t a2,
                                         uint32_t a3, uint32_t b0, uint32_t b1) {
    asm volatile(
        "mma.sync.aligned.m16n8k16.row.col.f32.f16.f16.f32 "
        "{%0,%1,%2,%3}, {%4,%5,%6,%7}, {%8,%9}, {%0,%1,%2,%3};"
        : "+f"(d[0]), "+f"(d[1]), "+f"(d[2]), "+f"(d[3])
        : "r"(a0), "r"(a1), "r"(a2), "r"(a3), "r"(b0), "r"(b1));
}
// .cg: L2-only — weight tiles are L2-resident and shared by all CTAs.
#define CP_ASYNC16_CG(dst, src) \
    asm volatile("cp.async.cg.shared.global [%0], [%1], 16;" :: "r"(dst), "l"(src))
#define CP_COMMIT() asm volatile("cp.async.commit_group;" ::: "memory")
#define CP_WAIT0() asm volatile("cp.async.wait_group 0;" ::: "memory")

__device__ __forceinline__ uint32_t pk2h(float a, float b) {
    __half2 h = __floats2half2_rn(a, b);
    return *(uint32_t*)&h;
}

// ======================= fp16 B-split warp-MMA GEMM =======================
// C = act( sum_seg A_seg @ (Wh+Wl)_seg^T + bias )
// A: fp16 activations (rounded once at producer). W: exact hi/lo fp16 split.
// CTA tile 128x64 (grid.y = 2 N-halves), warp tile 64x16, BK=32, dbl-buffer.
// 32-reg accumulators -> 3 CTAs/SM (24 warps) at the 85-reg cap.
#define ASTR 40
#define A_OFF 0
#define BH_OFF 5120
#define BL_OFF 7680
#define BUF_ELE 10240
#define GEMM_SMEM (2 * BUF_ELE * 2)   // 40960 B

template <int NSEG, int RELU>
__global__ void __launch_bounds__(256, 3) mma_gemm(
    const __half* __restrict__ X, const __half* __restrict__ Agg,
    const __half* __restrict__ Wh, const __half* __restrict__ Wl,
    const float* __restrict__ bias, __half* __restrict__ C, int M) {
    extern __shared__ __half sm[];
    const int KTOT = NSEG * 128;
    const int CHUNKS = NSEG * 4;
    int tid = threadIdx.x, lane = tid & 31, wid = tid >> 5;
    int warpM = wid & 1, warpN = wid >> 1;          // warp tile 64x16
    int rowBlock = blockIdx.x * 128;
    int nOff = blockIdx.y * 64;
    uint32_t smb = smem_to_u32(sm);

    int arow = tid >> 1, ahalf = tid & 1;           // A: 2 thr/row, 16 halves each
    int brow = tid >> 2, bq = tid & 3;              // B: 4 thr/row, 8 halves each
    size_t grow = (size_t)(rowBlock + arow);

    float acc[4][2][4];
#pragma unroll
    for (int i = 0; i < 4; i++)
#pragma unroll
        for (int j = 0; j < 2; j++)
#pragma unroll
            for (int k = 0; k < 4; k++) acc[i][j][k] = 0.f;

    uint4 ar0, ar1;

    // ---- prologue: stage chunk 0 into buf 0 ----
    {
        const uint4* ap = (const uint4*)(X + grow * 128 + ahalf * 16);
        ar0 = ap[0]; ar1 = ap[1];
        const __half* wh = Wh + (size_t)(nOff + brow) * KTOT + bq * 8;
        const __half* wl = Wl + (size_t)(nOff + brow) * KTOT + bq * 8;
        uint32_t dH = smb + (uint32_t)(BH_OFF + brow * ASTR + bq * 8) * 2;
        uint32_t dL = smb + (uint32_t)(BL_OFF + brow * ASTR + bq * 8) * 2;
        CP_ASYNC16_CG(dH, wh);
        CP_ASYNC16_CG(dL, wl);
        CP_COMMIT();
        uint4* dst = (uint4*)(sm + A_OFF + arow * ASTR + ahalf * 16);
        dst[0] = ar0; dst[1] = ar1;
    }
    CP_WAIT0();
    __syncthreads();

    int lr8 = lane & 7, lb = lane >> 3;
    // merged-B ldmatrix lane mapping: one x4 covers 16 rows x 16 cols
    int bRowL = ((lane >> 4) << 3) + lr8;     // 0..15
    int bColL = ((lane >> 3) & 1) * 8;        // 0 or 8

    for (int c = 0; c < CHUNKS; c++) {
        int buf = c & 1;
        uint32_t base = smb + (uint32_t)buf * BUF_ELE * 2;
        bool hasNext = (c + 1) < CHUNKS;

        if (hasNext) {
            int cn = c + 1;
            int seg = cn >> 2, kin = (cn & 3) * 32;
            const __half* wh = Wh + (size_t)(nOff + brow) * KTOT + cn * 32 + bq * 8;
            const __half* wl = Wl + (size_t)(nOff + brow) * KTOT + cn * 32 + bq * 8;
            uint32_t off = (uint32_t)((buf ^ 1) * BUF_ELE) * 2;
            uint32_t dH = smb + off + (uint32_t)(BH_OFF + brow * ASTR + bq * 8) * 2;
            uint32_t dL = smb + off + (uint32_t)(BL_OFF + brow * ASTR + bq * 8) * 2;
            CP_ASYNC16_CG(dH, wh);
            CP_ASYNC16_CG(dL, wl);
            CP_COMMIT();
            const __half* As = (NSEG == 1 || seg == 0) ? X : Agg + (size_t)(seg - 1) * NN * 128;
            const uint4* ap = (const uint4*)(As + grow * 128 + kin + ahalf * 16);
            ar0 = ap[0]; ar1 = ap[1];
        }

        // ---- MMA on current buffer ----
        {
            uint32_t aB = base + A_OFF * 2;
            uint32_t bH = base + BH_OFF * 2, bL = base + BL_OFF * 2;
#pragma unroll
            for (int ks = 0; ks < 2; ks++) {
                uint32_t bhf[2][2], blf[2][2];
                {
                    int bRow = warpN * 16 + bRowL;
                    uint32_t o = (uint32_t)(bRow * ASTR + ks * 16 + bColL) * 2;
                    ldsm_x4(bhf[0][0], bhf[0][1], bhf[1][0], bhf[1][1], bH + o);
                    ldsm_x4(blf[0][0], blf[0][1], blf[1][0], blf[1][1], bL + o);
                }
                int aCol = ks * 16 + (lb >> 1) * 8;
#pragma unroll
                for (int mi = 0; mi < 4; mi++) {
                    int aRow = warpM * 64 + mi * 16 + (lb & 1) * 8 + lr8;
                    uint32_t o = (uint32_t)(aRow * ASTR + aCol) * 2;
                    uint32_t a0, a1, a2, a3;
                    ldsm_x4(a0, a1, a2, a3, aB + o);
#pragma unroll
                    for (int ni = 0; ni < 2; ni++) {
                        mma16816(acc[mi][ni], a0, a1, a2, a3, bhf[ni][0], bhf[ni][1]);
                        mma16816(acc[mi][ni], a0, a1, a2, a3, blf[ni][0], blf[ni][1]);
                    }
                }
            }
        }

        if (hasNext) {
            uint4* dst = (uint4*)(sm + (buf ^ 1) * BUF_ELE + A_OFF + arow * ASTR + ahalf * 16);
            dst[0] = ar0; dst[1] = ar1;
        }
        CP_WAIT0();
        __syncthreads();
    }

    // ---- epilogue: bias + act, round to fp16 plane (bias hoisted) ----
    int gid = lane >> 2, qid = lane & 3;
    float bx[2][2];
#pragma unroll
    for (int ni = 0; ni < 2; ni++) {
        int cb = nOff + warpN * 16 + ni * 8 + qid * 2;
        bx[ni][0] = bias[cb];
        bx[ni][1] = bias[cb + 1];
    }
#pragma unroll
    for (int mi = 0; mi < 4; mi++) {
        int r0 = rowBlock + warpM * 64 + mi * 16 + gid;
        int r1 = r0 + 8;
#pragma unroll
        for (int ni = 0; ni < 2; ni++) {
            int cb = nOff + warpN * 16 + ni * 8 + qid * 2;
            float v0 = acc[mi][ni][0] + bx[ni][0], v1 = acc[mi][ni][1] + bx[ni][1];
            float v2 = acc[mi][ni][2] + bx[ni][0], v3 = acc[mi][ni][3] + bx[ni][1];
            if (RELU) { v0 = lrelu(v0); v1 = lrelu(v1); v2 = lrelu(v2); v3 = lrelu(v3); }
            if (r0 < M) *(uint32_t*)(C + (size_t)r0 * 128 + cb) = pk2h(v0, v1);
            if (r1 < M) *(uint32_t*)(C + (size_t)r1 * 128 + cb) = pk2h(v2, v3);
        }
    }
}

// ======================= feature packing (fp32 -> fp16 plane) ================
__global__ void pack_kernel(const float* __restrict__ des, const float* __restrict__ tweet,
                            const float* __restrict__ nump, const float* __restrict__ catp,
                            __half* __restrict__ P) {
    long idx = blockIdx.x * 256L + threadIdx.x;
    if (idx >= (long)NN * 128) return;
    int row = (int)(idx >> 7), col = (int)(idx & 127);
    float v = 0.f;
    if (row < NU) {
        if (col < 100) v = des[(size_t)row * 100 + col];
        else if (col < 106) v = nump[(size_t)row * 6 + (col - 100)];
        else if (col < 117) v = catp[(size_t)row * 11 + (col - 106)];
    } else {
        if (col < 100) v = tweet[(size_t)(row - NU) * 100 + col];
    }
    P[idx] = __float2half_rn(v);
}

// ======================= weight pre-conversion (hi/lo split) =================
__global__ void prep_W_kernel(const float* __restrict__ Wd, const float* __restrict__ bd,
                              const float* __restrict__ Wn, const float* __restrict__ bn,
                              const float* __restrict__ Wc, const float* __restrict__ bc,
                              const float* __restrict__ Wt, const float* __restrict__ Win,
                              const float* __restrict__ root, const float* __restrict__ rw,
                              const float* __restrict__ Wo1) {
    int idx = blockIdx.x * 256 + threadIdx.x;
    if (idx >= BTOT + 128) return;
    if (idx >= BTOT) {
        int n = idx - BTOT;
        g_biasU[n] = (n < 64) ? bd[n] : (n < 96) ? bn[n - 64] : bc[n - 96];
        return;
    }
    float v = 0.f;
    if (idx < 16384) {  // featU blockdiag [n,k=128]
        int n = idx >> 7, k = idx & 127;
        if (n < 64) { if (k < 100) v = Wd[n * 100 + k]; }
        else if (n < 96) { if (k >= 100 && k < 106) v = Wn[(n - 64) * 6 + (k - 100)]; }
        else { if (k >= 106 && k < 117) v = Wc[(n - 96) * 11 + (k - 106)]; }
    } else if (idx < 32768) {  // featT
        int l = idx - 16384;
        int n = l >> 7, k = l & 127;
        if (k < 100) v = Wt[n * 100 + k];
    } else if (idx < 49152) {  // lin
        v = Win[idx - 32768];
    } else if (idx < 98304) {  // conv: [n, k=384]: seg0 root^T, seg1/2 rw^T
        int l = idx - 49152;
        int n = l / 384, k = l % 384;
        if (k < 128) v = root[k * 128 + n];
        else if (k < 256) v = rw[(k - 128) * 128 + n];
        else v = rw[16384 + (k - 256) * 128 + n];
    } else {  // o1
        v = Wo1[idx - 98304];
    }
    __half h = __float2half_rn(v);
    g_Wh[idx] = h;
    g_Wl[idx] = __float2half_rn(v - __half2float(h));
}

// ======================= CSR build =======================
__global__ void zero2_kernel(int* __restrict__ a, int* __restrict__ b, int n) {
    int i = blockIdx.x * 256 + threadIdx.x;
    if (i < n) { a[i] = 0; b[i] = 0; }
}

__global__ void count_kernel(const int* __restrict__ ei, const int* __restrict__ et,
                             int* __restrict__ cnt) {
    int e = blockIdx.x * 256 + threadIdx.x;
    if (e >= NE) return;
    atomicAdd(&cnt[et[e] * NN + ei[NE + e]], 1);
}

#define SCAN_BS 512
__global__ void scan1_kernel(const int* __restrict__ cnt, int* __restrict__ off,
                             int* __restrict__ bsum, int n) {
    __shared__ int sh[SCAN_BS];
    int t = threadIdx.x;
    int i = blockIdx.x * SCAN_BS + t;
    int v = (i < n) ? cnt[i] : 0;
    sh[t] = v;
    __syncthreads();
#pragma unroll
    for (int d = 1; d < SCAN_BS; d <<= 1) {
        int x = (t >= d) ? sh[t - d] : 0;
        __syncthreads();
        sh[t] += x;
        __syncthreads();
    }
    if (i < n) off[i] = sh[t] - v;
    if (t == SCAN_BS - 1) bsum[blockIdx.x] = sh[t];
}

__global__ void scan2_kernel(int* __restrict__ bsum, int nb) {
    __shared__ int sh[1024];
    int t = threadIdx.x;
    int v = (t < nb) ? bsum[t] : 0;
    sh[t] = v;
    __syncthreads();
#pragma unroll
    for (int d = 1; d < 1024; d <<= 1) {
        int x = (t >= d) ? sh[t - d] : 0;
        __syncthreads();
        sh[t] += x;
        __syncthreads();
    }
    if (t < nb) bsum[t] = sh[t] - v;
}

__global__ void scan3_kernel(int* __restrict__ off, const int* __restrict__ bsum, int n) {
    int i = blockIdx.x * SCAN_BS + threadIdx.x;
    if (i < n) off[i] += bsum[blockIdx.x];
}

__global__ void fill_kernel(const int* __restrict__ ei, const int* __restrict__ et,
                            const int* __restrict__ off, int* __restrict__ cur,
                            int* __restrict__ esrc) {
    int e = blockIdx.x * 256 + threadIdx.x;
    if (e >= NE) return;
    int slot = et[e] * NN + ei[NE + e];
    int pos = off[slot] + atomicAdd(&cur[slot], 1);
    esrc[pos] = ei[e];
}

// ======================= CSR gather-mean aggregation (fp16 plane) ============
__global__ void agg_kernel(const __half* __restrict__ X, const int* __restrict__ off,
                           const int* __restrict__ cnt, const int* __restrict__ esrc,
                           __half* __restrict__ Agg) {
    int w = (blockIdx.x * blockDim.x + threadIdx.x) >> 5;
    int lane = threadIdx.x & 31;
    if (w >= NSLOT) return;
    int beg = off[w], deg = cnt[w];
    float4 acc = make_float4(0.f, 0.f, 0.f, 0.f);
    for (int i = 0; i < deg; i++) {
        int src = __ldg(&esrc[beg + i]);
        uint2 hu = *(const uint2*)(X + (size_t)src * 128 + lane * 4);
        float2 h0 = __half22float2(*(__half2*)&hu.x), h1 = __half22float2(*(__half2*)&hu.y);
        acc.x += h0.x; acc.y += h0.y; acc.z += h1.x; acc.w += h1.y;
    }
    float s = (deg > 0) ? 1.f / (float)deg : 0.f;
    uint2 o = make_uint2(pk2h(acc.x * s, acc.y * s), pk2h(acc.z * s, acc.w * s));
    *(uint2*)(Agg + (size_t)w * 128 + lane * 4) = o;
}

// ======================= final 128->2 projection =======================
__global__ void out_kernel(const __half* __restrict__ X, const float* __restrict__ W2,
                           const float* __restrict__ b2, float* __restrict__ out) {
    int gw = (blockIdx.x * blockDim.x + threadIdx.x) >> 5;
    int lane = threadIdx.x & 31;
    if (gw >= NN) return;
    uint2 hu = *(const uint2*)(X + (size_t)gw * 128 + lane * 4);
    float2 h0 = __half22float2(*(__half2*)&hu.x), h1 = __half22float2(*(__half2*)&hu.y);
    float4 w0 = *(const float4*)(W2 + lane * 4);
    float4 w1 = *(const float4*)(W2 + 128 + lane * 4);
    float s0 = h0.x * w0.x + h0.y * w0.y + h1.x * w0.z + h1.y * w0.w;
    float s1 = h0.x * w1.x + h0.y * w1.y + h1.x * w1.z + h1.y * w1.w;
#pragma unroll
    for (int off = 16; off; off >>= 1) {
        s0 += __shfl_xor_sync(0xffffffffu, s0, off);
        s1 += __shfl_xor_sync(0xffffffffu, s1, off);
    }
    if (lane == 0) {
        out[(size_t)gw * 2 + 0] = s0 + b2[0];
        out[(size_t)gw * 2 + 1] = s1 + b2[1];
    }
}

// ---------------------------------------------------------------------------
extern "C" void kernel_launch(void* const* d_in, const int* in_sizes, int n_in,
                              void* d_out, int out_size) {
    const float* des   = (const float*)d_in[0];
    const float* tweet = (const float*)d_in[1];
    const float* nump  = (const float*)d_in[2];
    const float* catp  = (const float*)d_in[3];
    const int*   ei    = (const int*)d_in[4];
    const int*   et    = (const int*)d_in[5];
    const float* Wd  = (const float*)d_in[6];  const float* bd  = (const float*)d_in[7];
    const float* Wn  = (const float*)d_in[8];  const float* bn  = (const float*)d_in[9];
    const float* Wc  = (const float*)d_in[10]; const float* bc  = (const float*)d_in[11];
    const float* Wt  = (const float*)d_in[12]; const float* bt  = (const float*)d_in[13];
    const float* Win = (const float*)d_in[14]; const float* bin = (const float*)d_in[15];
    const float* rw    = (const float*)d_in[16];
    const float* rroot = (const float*)d_in[17];
    const float* rbias = (const float*)d_in[18];
    const float* Wo1 = (const float*)d_in[19]; const float* bo1 = (const float*)d_in[20];
    const float* Wo2 = (const float*)d_in[21]; const float* bo2 = (const float*)d_in[22];
    float* out = (float*)d_out;

    __half *pX1, *pX2, *pG, *pWh, *pWl;
    float* pBiasU;
    int *pCnt, *pOff, *pCur, *pBsum, *pEsrc;
    cudaGetSymbolAddress((void**)&pX1, g_X1);
    cudaGetSymbolAddress((void**)&pX2, g_X2);
    cudaGetSymbolAddress((void**)&pG, g_agg);
    cudaGetSymbolAddress((void**)&pWh, g_Wh);
    cudaGetSymbolAddress((void**)&pWl, g_Wl);
    cudaGetSymbolAddress((void**)&pBiasU, g_biasU);
    cudaGetSymbolAddress((void**)&pCnt, g_cnt);
    cudaGetSymbolAddress((void**)&pOff, g_off);
    cudaGetSymbolAddress((void**)&pCur, g_cur);
    cudaGetSymbolAddress((void**)&pBsum, g_bsum);
    cudaGetSymbolAddress((void**)&pEsrc, g_esrc);

    const int GU = (NU + 127) / 128;   // 782
    const int GN = (NN + 127) / 128;   // 1563
    const int SCAN_NB = (NSLOT + SCAN_BS - 1) / SCAN_BS;
    dim3 gU(GU, 2), gN(GN, 2);

    // 1-2: pack inputs -> X2 ; pre-convert weights (hi/lo)
    pack_kernel<<<(NN * 128 + 255) / 256, 256>>>(des, tweet, nump, catp, pX2);
    prep_W_kernel<<<(BTOT + 128 + 255) / 256, 256>>>(Wd, bd, Wn, bn, Wc, bc, Wt, Win,
                                                     rroot, rw, Wo1);
    // 3-5: feature MLP GEMMs -> X1 ; lin: X1 -> X2
    mma_gemm<1, 1><<<gU, 256, GEMM_SMEM>>>(pX2, nullptr, pWh, pWl, pBiasU, pX1, NU);
    mma_gemm<1, 1><<<gU, 256, GEMM_SMEM>>>(pX2 + (size_t)NU * 128, nullptr,
                                           pWh + 16384, pWl + 16384, bt,
                                           pX1 + (size_t)NU * 128, NU);
    mma_gemm<1, 1><<<gN, 256, GEMM_SMEM>>>(pX1, nullptr, pWh + 32768, pWl + 32768,
                                           bin, pX2, NN);
    // 6-11: CSR build (once; reused by both convs)
    zero2_kernel<<<(NSLOT + 255) / 256, 256>>>(pCnt, pCur, NSLOT);
    count_kernel<<<(NE + 255) / 256, 256>>>(ei, et, pCnt);
    scan1_kernel<<<SCAN_NB, SCAN_BS>>>(pCnt, pOff, pBsum, NSLOT);
    scan2_kernel<<<1, 1024>>>(pBsum, SCAN_NB);
    scan3_kernel<<<SCAN_NB, SCAN_BS>>>(pOff, pBsum, NSLOT);
    fill_kernel<<<(NE + 255) / 256, 256>>>(ei, et, pOff, pCur, pEsrc);

    // conv1: X2 -> X1
    agg_kernel<<<NSLOT / 8, 256>>>(pX2, pOff, pCnt, pEsrc, pG);
    mma_gemm<3, 0><<<gN, 256, GEMM_SMEM>>>(pX2, pG, pWh + 49152, pWl + 49152,
                                           rbias, pX1, NN);
    // conv2: X1 -> X2
    agg_kernel<<<NSLOT / 8, 256>>>(pX1, pOff, pCnt, pEsrc, pG);
    mma_gemm<3, 0><<<gN, 256, GEMM_SMEM>>>(pX1, pG, pWh + 49152, pWl + 49152,
                                           rbias, pX2, NN);
    // o1: X2 -> X1
    mma_gemm<1, 1><<<gN, 256, GEMM_SMEM>>>(pX2, nullptr, pWh + 98304, pWl + 98304,
                                           bo1, pX1, NN);
    // out = x @ W_o2^T + b_o2
    out_kernel<<<NN / 8, 256>>>(pX1, Wo2, bo2, out);
}

// round 13
// speedup vs baseline: 1.0001x; 1.0001x over previous
#include <cuda_runtime.h>
#include <cuda_fp16.h>
#include <cstdint>

#define NU 100000
#define NT 100000
#define NN 200000
#define NE 600000
#define NSLOT (2 * NN)
#define NPAD (NN + 192)          // row padding: tail CTAs may read past M

// ---- scratch (device globals; no runtime allocation) ----
// activations: single fp16 plane (rounded once per layer)
__device__ __align__(16) __half g_X1[(size_t)NPAD * 128];
__device__ __align__(16) __half g_X2[(size_t)NPAD * 128];
__device__ __align__(16) __half g_agg[(size_t)(NSLOT + 192) * 128];
// CSR structures
__device__ int g_cnt[NSLOT];
__device__ int g_off[NSLOT];
__device__ int g_cur[NSLOT];
__device__ int g_bsum[1024];
__device__ int g_esrc[NE];
// pre-converted weights, fp16 hi/lo planes, [N=128, Ktot] K-major rows:
// featU @0 (Ktot128), featT @16384, lin @32768, conv @49152 (Ktot384), o1 @98304
#define BTOT 114688
__device__ __align__(16) __half g_Wh[BTOT];
__device__ __align__(16) __half g_Wl[BTOT];
__device__ float g_biasU[128];

__device__ __forceinline__ float lrelu(float x) { return x > 0.f ? x : 0.01f * x; }

// ======================= PTX helpers (portable sm_80+) =======================
__device__ __forceinline__ uint32_t smem_to_u32(const void* p) {
    uint32_t a;
    asm("{ .reg .u64 t; cvta.to.shared.u64 t, %1; cvt.u32.u64 %0, t; }" : "=r"(a) : "l"(p));
    return a;
}
__device__ __forceinline__ void ldsm_x4(uint32_t& r0, uint32_t& r1, uint32_t& r2,
                                        uint32_t& r3, uint32_t a) {
    asm volatile("ldmatrix.sync.aligned.m8n8.x4.shared.b16 {%0,%1,%2,%3}, [%4];"
                 : "=r"(r0), "=r"(r1), "=r"(r2), "=r"(r3) : "r"(a));
}
__device__ __forceinline__ void mma16816(float* d, uint32_t a0, uint32_t a1, uint32_t a2,
                                         uint32_t a3, uint32_t b0, uint32_t b1) {
    asm volatile(
        "mma.sync.aligned.m16n8k16.row.col.f32.f16.f16.f32 "
        "{%0,%1,%2,%3}, {%4,%5,%6,%7}, {%8,%9}, {%0,%1,%2,%3};"
        : "+f"(d[0]), "+f"(d[1]), "+f"(d[2]), "+f"(d[3])
        : "r"(a0), "r"(a1), "r"(a2), "r"(a3), "r"(b0), "r"(b1));
}
// .cg: L2-only, 16B. Weights are L2-resident+shared; A rows are streaming
// (read exactly once per GEMM) — keep both off the L1 fill path.
#define CP_ASYNC16_CG(dst, src) \
    asm volatile("cp.async.cg.shared.global [%0], [%1], 16;" :: "r"(dst), "l"(src))
#define CP_COMMIT() asm volatile("cp.async.commit_group;" ::: "memory")
#define CP_WAIT1() asm volatile("cp.async.wait_group 1;" ::: "memory")

__device__ __forceinline__ uint32_t pk2h(float a, float b) {
    __half2 h = __floats2half2_rn(a, b);
    return *(uint32_t*)&h;
}

// ======================= fp16 B-split warp-MMA GEMM =======================
// C = act( sum_seg A_seg @ (Wh+Wl)_seg^T + bias )
// A: fp16 activations (rounded once at producer). W: exact hi/lo fp16 split.
// Tile 128x128, warp 64x32, BK=32. 3-stage cp.async pipeline (wait_group 1):
// one chunk always in flight behind the MMA; all staging via cp.async.cg.
#define ASTR 40
#define A_OFF 0
#define BH_OFF 5120
#define BL_OFF 10240
#define BUF_ELE 15360
#define GEMM_SMEM (3 * BUF_ELE * 2)   // 92160 B, 2 CTAs/SM = 184 KB

template <int NSEG, int RELU>
__global__ void __launch_bounds__(256, 2) mma_gemm(
    const __half* __restrict__ X, const __half* __restrict__ Agg,
    const __half* __restrict__ Wh, const __half* __restrict__ Wl,
    const float* __restrict__ bias, __half* __restrict__ C, int M) {
    extern __shared__ __half sm[];
    const int KTOT = NSEG * 128;
    const int CHUNKS = NSEG * 4;
    int tid = threadIdx.x, lane = tid & 31, wid = tid >> 5;
    int warpM = wid & 1, warpN = wid >> 1;
    int rowBlock = blockIdx.x * 128;
    uint32_t smb = smem_to_u32(sm);

    int arow = tid >> 1, ahalf = tid & 1;
    size_t grow = (size_t)(rowBlock + arow);

    float acc[4][4][4];
#pragma unroll
    for (int i = 0; i < 4; i++)
#pragma unroll
        for (int j = 0; j < 4; j++)
#pragma unroll
            for (int k = 0; k < 4; k++) acc[i][j][k] = 0.f;

    // ---- stage helper offsets (same addressing for all chunks) ----
    uint32_t sA = (uint32_t)(A_OFF + arow * ASTR + ahalf * 16) * 2;
    uint32_t sBH = (uint32_t)(BH_OFF + arow * ASTR + ahalf * 16) * 2;
    uint32_t sBL = (uint32_t)(BL_OFF + arow * ASTR + ahalf * 16) * 2;

    // ---- prologue: stage chunks 0 and 1 ----
#pragma unroll
    for (int cn = 0; cn < 2; cn++) {
        int seg = cn >> 2, kin = (cn & 3) * 32;
        const __half* As = (NSEG == 1 || seg == 0) ? X : Agg + (size_t)(seg - 1) * NN * 128;
        const __half* ap = As + grow * 128 + kin + ahalf * 16;
        const __half* wh = Wh + (size_t)arow * KTOT + cn * 32 + ahalf * 16;
        const __half* wl = Wl + (size_t)arow * KTOT + cn * 32 + ahalf * 16;
        uint32_t bb = smb + (uint32_t)(cn % 3) * BUF_ELE * 2;
        CP_ASYNC16_CG(bb + sA, ap); CP_ASYNC16_CG(bb + sA + 16, ap + 8);
        CP_ASYNC16_CG(bb + sBH, wh); CP_ASYNC16_CG(bb + sBH + 16, wh + 8);
        CP_ASYNC16_CG(bb + sBL, wl); CP_ASYNC16_CG(bb + sBL + 16, wl + 8);
        CP_COMMIT();
    }

    int lr8 = lane & 7, lb = lane >> 3;
    // merged-B ldmatrix lane mapping (per pair p: frags ni=2p, 2p+1)
    int bRowL = ((lane >> 4) << 3) + lr8;     // 0..15
    int bColL = ((lane >> 3) & 1) * 8;        // 0 or 8

    for (int c = 0; c < CHUNKS; c++) {
        CP_WAIT1();            // groups <= c complete
        __syncthreads();       // all warps done with buffer (c-1)%3 MMA; chunk c visible

        int cn = c + 2;
        if (cn < CHUNKS) {
            int seg = cn >> 2, kin = (cn & 3) * 32;
            const __half* As = (NSEG == 1 || seg == 0) ? X : Agg + (size_t)(seg - 1) * NN * 128;
            const __half* ap = As + grow * 128 + kin + ahalf * 16;
            const __half* wh = Wh + (size_t)arow * KTOT + cn * 32 + ahalf * 16;
            const __half* wl = Wl + (size_t)arow * KTOT + cn * 32 + ahalf * 16;
            uint32_t bb = smb + (uint32_t)(cn % 3) * BUF_ELE * 2;
            CP_ASYNC16_CG(bb + sA, ap); CP_ASYNC16_CG(bb + sA + 16, ap + 8);
            CP_ASYNC16_CG(bb + sBH, wh); CP_ASYNC16_CG(bb + sBH + 16, wh + 8);
            CP_ASYNC16_CG(bb + sBL, wl); CP_ASYNC16_CG(bb + sBL + 16, wl + 8);
        }
        CP_COMMIT();           // empty group when no issues: keeps wait accounting

        // ---- MMA on buffer c%3 ----
        uint32_t base = smb + (uint32_t)(c % 3) * BUF_ELE * 2;
        uint32_t aB = base + A_OFF * 2;
        uint32_t bH = base + BH_OFF * 2, bL = base + BL_OFF * 2;
#pragma unroll
        for (int ks = 0; ks < 2; ks++) {
            uint32_t bhf[4][2], blf[4][2];
#pragma unroll
            for (int p = 0; p < 2; p++) {
                int bRow = warpN * 32 + p * 16 + bRowL;
                uint32_t o = (uint32_t)(bRow * ASTR + ks * 16 + bColL) * 2;
                ldsm_x4(bhf[2 * p][0], bhf[2 * p][1], bhf[2 * p + 1][0],
                        bhf[2 * p + 1][1], bH + o);
                ldsm_x4(blf[2 * p][0], blf[2 * p][1], blf[2 * p + 1][0],
                        blf[2 * p + 1][1], bL + o);
            }
            int aCol = ks * 16 + (lb >> 1) * 8;
#pragma unroll
            for (int mi = 0; mi < 4; mi++) {
                int aRow = warpM * 64 + mi * 16 + (lb & 1) * 8 + lr8;
                uint32_t o = (uint32_t)(aRow * ASTR + aCol) * 2;
                uint32_t a0, a1, a2, a3;
                ldsm_x4(a0, a1, a2, a3, aB + o);
#pragma unroll
                for (int ni = 0; ni < 4; ni++) {
                    mma16816(acc[mi][ni], a0, a1, a2, a3, bhf[ni][0], bhf[ni][1]);
                    mma16816(acc[mi][ni], a0, a1, a2, a3, blf[ni][0], blf[ni][1]);
                }
            }
        }
    }

    // ---- epilogue: bias + act, round to fp16 plane (bias hoisted) ----
    int gid = lane >> 2, qid = lane & 3;
    float bx[4][2];
#pragma unroll
    for (int ni = 0; ni < 4; ni++) {
        int cb = warpN * 32 + ni * 8 + qid * 2;
        bx[ni][0] = bias[cb];
        bx[ni][1] = bias[cb + 1];
    }
#pragma unroll
    for (int mi = 0; mi < 4; mi++) {
        int r0 = rowBlock + warpM * 64 + mi * 16 + gid;
        int r1 = r0 + 8;
#pragma unroll
        for (int ni = 0; ni < 4; ni++) {
            int cb = warpN * 32 + ni * 8 + qid * 2;
            float v0 = acc[mi][ni][0] + bx[ni][0], v1 = acc[mi][ni][1] + bx[ni][1];
            float v2 = acc[mi][ni][2] + bx[ni][0], v3 = acc[mi][ni][3] + bx[ni][1];
            if (RELU) { v0 = lrelu(v0); v1 = lrelu(v1); v2 = lrelu(v2); v3 = lrelu(v3); }
            if (r0 < M) *(uint32_t*)(C + (size_t)r0 * 128 + cb) = pk2h(v0, v1);
            if (r1 < M) *(uint32_t*)(C + (size_t)r1 * 128 + cb) = pk2h(v2, v3);
        }
    }
}

// ======================= feature packing (fp32 -> fp16 plane) ================
__global__ void pack_kernel(const float* __restrict__ des, const float* __restrict__ tweet,
                            const float* __restrict__ nump, const float* __restrict__ catp,
                            __half* __restrict__ P) {
    long idx = blockIdx.x * 256L + threadIdx.x;
    if (idx >= (long)NN * 128) return;
    int row = (int)(idx >> 7), col = (int)(idx & 127);
    float v = 0.f;
    if (row < NU) {
        if (col < 100) v = des[(size_t)row * 100 + col];
        else if (col < 106) v = nump[(size_t)row * 6 + (col - 100)];
        else if (col < 117) v = catp[(size_t)row * 11 + (col - 106)];
    } else {
        if (col < 100) v = tweet[(size_t)(row - NU) * 100 + col];
    }
    P[idx] = __float2half_rn(v);
}

// ======================= weight pre-conversion (hi/lo split) =================
__global__ void prep_W_kernel(const float* __restrict__ Wd, const float* __restrict__ bd,
                              const float* __restrict__ Wn, const float* __restrict__ bn,
                              const float* __restrict__ Wc, const float* __restrict__ bc,
                              const float* __restrict__ Wt, const float* __restrict__ Win,
                              const float* __restrict__ root, const float* __restrict__ rw,
                              const float* __restrict__ Wo1) {
    int idx = blockIdx.x * 256 + threadIdx.x;
    if (idx >= BTOT + 128) return;
    if (idx >= BTOT) {
        int n = idx - BTOT;
        g_biasU[n] = (n < 64) ? bd[n] : (n < 96) ? bn[n - 64] : bc[n - 96];
        return;
    }
    float v = 0.f;
    if (idx < 16384) {  // featU blockdiag [n,k=128]
        int n = idx >> 7, k = idx & 127;
        if (n < 64) { if (k < 100) v = Wd[n * 100 + k]; }
        else if (n < 96) { if (k >= 100 && k < 106) v = Wn[(n - 64) * 6 + (k - 100)]; }
        else { if (k >= 106 && k < 117) v = Wc[(n - 96) * 11 + (k - 106)]; }
    } else if (idx < 32768) {  // featT
        int l = idx - 16384;
        int n = l >> 7, k = l & 127;
        if (k < 100) v = Wt[n * 100 + k];
    } else if (idx < 49152) {  // lin
        v = Win[idx - 32768];
    } else if (idx < 98304) {  // conv: [n, k=384]: seg0 root^T, seg1/2 rw^T
        int l = idx - 49152;
        int n = l / 384, k = l % 384;
        if (k < 128) v = root[k * 128 + n];
        else if (k < 256) v = rw[(k - 128) * 128 + n];
        else v = rw[16384 + (k - 256) * 128 + n];
    } else {  // o1
        v = Wo1[idx - 98304];
    }
    __half h = __float2half_rn(v);
    g_Wh[idx] = h;
    g_Wl[idx] = __float2half_rn(v - __half2float(h));
}

// ======================= CSR build =======================
__global__ void zero2_kernel(int* __restrict__ a, int* __restrict__ b, int n) {
    int i = blockIdx.x * 256 + threadIdx.x;
    if (i < n) { a[i] = 0; b[i] = 0; }
}

__global__ void count_kernel(const int* __restrict__ ei, const int* __restrict__ et,
                             int* __restrict__ cnt) {
    int e = blockIdx.x * 256 + threadIdx.x;
    if (e >= NE) return;
    atomicAdd(&cnt[et[e] * NN + ei[NE + e]], 1);
}

#define SCAN_BS 512
__global__ void scan1_kernel(const int* __restrict__ cnt, int* __restrict__ off,
                             int* __restrict__ bsum, int n) {
    __shared__ int sh[SCAN_BS];
    int t = threadIdx.x;
    int i = blockIdx.x * SCAN_BS + t;
    int v = (i < n) ? cnt[i] : 0;
    sh[t] = v;
    __syncthreads();
#pragma unroll
    for (int d = 1; d < SCAN_BS; d <<= 1) {
        int x = (t >= d) ? sh[t - d] : 0;
        __syncthreads();
        sh[t] += x;
        __syncthreads();
    }
    if (i < n) off[i] = sh[t] - v;
    if (t == SCAN_BS - 1) bsum[blockIdx.x] = sh[t];
}

__global__ void scan2_kernel(int* __restrict__ bsum, int nb) {
    __shared__ int sh[1024];
    int t = threadIdx.x;
    int v = (t < nb) ? bsum[t] : 0;
    sh[t] = v;
    __syncthreads();
#pragma unroll
    for (int d = 1; d < 1024; d <<= 1) {
        int x = (t >= d) ? sh[t - d] : 0;
        __syncthreads();
        sh[t] += x;
        __syncthreads();
    }
    if (t < nb) bsum[t] = sh[t] - v;
}

__global__ void scan3_kernel(int* __restrict__ off, const int* __restrict__ bsum, int n) {
    int i = blockIdx.x * SCAN_BS + threadIdx.x;
    if (i < n) off[i] += bsum[blockIdx.x];
}

__global__ void fill_kernel(const int* __restrict__ ei, const int* __restrict__ et,
                            const int* __restrict__ off, int* __restrict__ cur,
                            int* __restrict__ esrc) {
    int e = blockIdx.x * 256 + threadIdx.x;
    if (e >= NE) return;
    int slot = et[e] * NN + ei[NE + e];
    int pos = off[slot] + atomicAdd(&cur[slot], 1);
    esrc[pos] = ei[e];
}

// ======================= CSR gather-mean aggregation (fp16 plane) ============
__global__ void agg_kernel(const __half* __restrict__ X, const int* __restrict__ off,
                           const int* __restrict__ cnt, const int* __restrict__ esrc,
                           __half* __restrict__ Agg) {
    int w = (blockIdx.x * blockDim.x + threadIdx.x) >> 5;
    int lane = threadIdx.x & 31;
    if (w >= NSLOT) return;
    int beg = off[w], deg = cnt[w];
    float4 acc = make_float4(0.f, 0.f, 0.f, 0.f);
    for (int i = 0; i < deg; i++) {
        int src = __ldg(&esrc[beg + i]);
        uint2 hu = *(const uint2*)(X + (size_t)src * 128 + lane * 4);
        float2 h0 = __half22float2(*(__half2*)&hu.x), h1 = __half22float2(*(__half2*)&hu.y);
        acc.x += h0.x; acc.y += h0.y; acc.z += h1.x; acc.w += h1.y;
    }
    float s = (deg > 0) ? 1.f / (float)deg : 0.f;
    uint2 o = make_uint2(pk2h(acc.x * s, acc.y * s), pk2h(acc.z * s, acc.w * s));
    *(uint2*)(Agg + (size_t)w * 128 + lane * 4) = o;
}

// ======================= final 128->2 projection =======================
__global__ void out_kernel(const __half* __restrict__ X, const float* __restrict__ W2,
                           const float* __restrict__ b2, float* __restrict__ out) {
    int gw = (blockIdx.x * blockDim.x + threadIdx.x) >> 5;
    int lane = threadIdx.x & 31;
    if (gw >= NN) return;
    uint2 hu = *(const uint2*)(X + (size_t)gw * 128 + lane * 4);
    float2 h0 = __half22float2(*(__half2*)&hu.x), h1 = __half22float2(*(__half2*)&hu.y);
    float4 w0 = *(const float4*)(W2 + lane * 4);
    float4 w1 = *(const float4*)(W2 + 128 + lane * 4);
    float s0 = h0.x * w0.x + h0.y * w0.y + h1.x * w0.z + h1.y * w0.w;
    float s1 = h0.x * w1.x + h0.y * w1.y + h1.x * w1.z + h1.y * w1.w;
#pragma unroll
    for (int off = 16; off; off >>= 1) {
        s0 += __shfl_xor_sync(0xffffffffu, s0, off);
        s1 += __shfl_xor_sync(0xffffffffu, s1, off);
    }
    if (lane == 0) {
        out[(size_t)gw * 2 + 0] = s0 + b2[0];
        out[(size_t)gw * 2 + 1] = s1 + b2[1];
    }
}

// ---------------------------------------------------------------------------
extern "C" void kernel_launch(void* const* d_in, const int* in_sizes, int n_in,
                              void* d_out, int out_size) {
    const float* des   = (const float*)d_in[0];
    const float* tweet = (const float*)d_in[1];
    const float* nump  = (const float*)d_in[2];
    const float* catp  = (const float*)d_in[3];
    const int*   ei    = (const int*)d_in[4];
    const int*   et    = (const int*)d_in[5];
    const float* Wd  = (const float*)d_in[6];  const float* bd  = (const float*)d_in[7];
    const float* Wn  = (const float*)d_in[8];  const float* bn  = (const float*)d_in[9];
    const float* Wc  = (const float*)d_in[10]; const float* bc  = (const float*)d_in[11];
    const float* Wt  = (const float*)d_in[12]; const float* bt  = (const float*)d_in[13];
    const float* Win = (const float*)d_in[14]; const float* bin = (const float*)d_in[15];
    const float* rw    = (const float*)d_in[16];
    const float* rroot = (const float*)d_in[17];
    const float* rbias = (const float*)d_in[18];
    const float* Wo1 = (const float*)d_in[19]; const float* bo1 = (const float*)d_in[20];
    const float* Wo2 = (const float*)d_in[21]; const float* bo2 = (const float*)d_in[22];
    float* out = (float*)d_out;

    __half *pX1, *pX2, *pG, *pWh, *pWl;
    float* pBiasU;
    int *pCnt, *pOff, *pCur, *pBsum, *pEsrc;
    cudaGetSymbolAddress((void**)&pX1, g_X1);
    cudaGetSymbolAddress((void**)&pX2, g_X2);
    cudaGetSymbolAddress((void**)&pG, g_agg);
    cudaGetSymbolAddress((void**)&pWh, g_Wh);
    cudaGetSymbolAddress((void**)&pWl, g_Wl);
    cudaGetSymbolAddress((void**)&pBiasU, g_biasU);
    cudaGetSymbolAddress((void**)&pCnt, g_cnt);
    cudaGetSymbolAddress((void**)&pOff, g_off);
    cudaGetSymbolAddress((void**)&pCur, g_cur);
    cudaGetSymbolAddress((void**)&pBsum, g_bsum);
    cudaGetSymbolAddress((void**)&pEsrc, g_esrc);

    cudaFuncSetAttribute(mma_gemm<1, 1>, cudaFuncAttributeMaxDynamicSharedMemorySize, GEMM_SMEM);
    cudaFuncSetAttribute(mma_gemm<3, 0>, cudaFuncAttributeMaxDynamicSharedMemorySize, GEMM_SMEM);

    const int GU = (NU + 127) / 128;   // 782
    const int GN = (NN + 127) / 128;   // 1563
    const int SCAN_NB = (NSLOT + SCAN_BS - 1) / SCAN_BS;

    // 1-2: pack inputs -> X2 ; pre-convert weights (hi/lo)
    pack_kernel<<<(NN * 128 + 255) / 256, 256>>>(des, tweet, nump, catp, pX2);
    prep_W_kernel<<<(BTOT + 128 + 255) / 256, 256>>>(Wd, bd, Wn, bn, Wc, bc, Wt, Win,
                                                     rroot, rw, Wo1);
    // 3-5: feature MLP GEMMs -> X1 ; lin: X1 -> X2
    mma_gemm<1, 1><<<GU, 256, GEMM_SMEM>>>(pX2, nullptr, pWh, pWl, pBiasU, pX1, NU);
    mma_gemm<1, 1><<<GU, 256, GEMM_SMEM>>>(pX2 + (size_t)NU * 128, nullptr,
                                           pWh + 16384, pWl + 16384, bt,
                                           pX1 + (size_t)NU * 128, NU);
    mma_gemm<1, 1><<<GN, 256, GEMM_SMEM>>>(pX1, nullptr, pWh + 32768, pWl + 32768,
                                           bin, pX2, NN);
    // 6-11: CSR build (once; reused by both convs)
    zero2_kernel<<<(NSLOT + 255) / 256, 256>>>(pCnt, pCur, NSLOT);
    count_kernel<<<(NE + 255) / 256, 256>>>(ei, et, pCnt);
    scan1_kernel<<<SCAN_NB, SCAN_BS>>>(pCnt, pOff, pBsum, NSLOT);
    scan2_kernel<<<1, 1024>>>(pBsum, SCAN_NB);
    scan3_kernel<<<SCAN_NB, SCAN_BS>>>(pOff, pBsum, NSLOT);
    fill_kernel<<<(NE + 255) / 256, 256>>>(ei, et, pOff, pCur, pEsrc);

    // conv1: X2 -> X1
    agg_kernel<<<NSLOT / 8, 256>>>(pX2, pOff, pCnt, pEsrc, pG);
    mma_gemm<3, 0><<<GN, 256, GEMM_SMEM>>>(pX2, pG, pWh + 49152, pWl + 49152,
                                           rbias, pX1, NN);
    // conv2: X1 -> X2
    agg_kernel<<<NSLOT / 8, 256>>>(pX1, pOff, pCnt, pEsrc, pG);
    mma_gemm<3, 0><<<GN, 256, GEMM_SMEM>>>(pX1, pG, pWh + 49152, pWl + 49152,
                                           rbias, pX2, NN);
    // o1: X2 -> X1
    mma_gemm<1, 1><<<GN, 256, GEMM_SMEM>>>(pX2, nullptr, pWh + 98304, pWl + 98304,
                                           bo1, pX1, NN);
    // out = x @ W_o2^T + b_o2
    out_kernel<<<NN / 8, 256>>>(pX1, Wo2, bo2, out);
}

// round 15
// speedup vs baseline: 1.0849x; 1.0848x over previous
#include <cuda_runtime.h>
#include <cuda_fp16.h>
#include <cstdint>

#define NU 100000
#define NT 100000
#define NN 200000
#define NE 600000
#define NSLOT (2 * NN)
#define NPAD (NN + 192)          // row padding: tail CTAs may read past M

// ---- scratch (device globals; no runtime allocation) ----
__device__ __align__(16) __half g_X1[(size_t)NPAD * 128];
__device__ __align__(16) __half g_X2[(size_t)NPAD * 128];
__device__ __align__(16) __half g_agg[(size_t)(NSLOT + 192) * 128];
// CSR structures
__device__ int g_cnt[NSLOT];
__device__ int g_off[NSLOT];
__device__ int g_cur[NSLOT];
__device__ int g_bsum[1024];
__device__ int g_esrc[NE];
// pre-converted weights, fp16 hi/lo planes, [N=128, Ktot] K-major rows:
// featU @0 (Ktot128), featT @16384, lin @32768, conv @49152 (Ktot384), o1 @98304
#define BTOT 114688
__device__ __align__(16) __half g_Wh[BTOT];
__device__ __align__(16) __half g_Wl[BTOT];
__device__ float g_biasU[128];

__device__ __forceinline__ float lrelu(float x) { return x > 0.f ? x : 0.01f * x; }

// ======================= PTX helpers (portable sm_80+) =======================
__device__ __forceinline__ uint32_t smem_to_u32(const void* p) {
    uint32_t a;
    asm("{ .reg .u64 t; cvta.to.shared.u64 t, %1; cvt.u32.u64 %0, t; }" : "=r"(a) : "l"(p));
    return a;
}
__device__ __forceinline__ void ldsm_x4(uint32_t& r0, uint32_t& r1, uint32_t& r2,
                                        uint32_t& r3, uint32_t a) {
    asm volatile("ldmatrix.sync.aligned.m8n8.x4.shared.b16 {%0,%1,%2,%3}, [%4];"
                 : "=r"(r0), "=r"(r1), "=r"(r2), "=r"(r3) : "r"(a));
}
__device__ __forceinline__ void mma16816(float* d, uint32_t a0, uint32_t a1, uint32_t a2,
                                         uint32_t a3, uint32_t b0, uint32_t b1) {
    asm volatile(
        "mma.sync.aligned.m16n8k16.row.col.f32.f16.f16.f32 "
        "{%0,%1,%2,%3}, {%4,%5,%6,%7}, {%8,%9}, {%0,%1,%2,%3};"
        : "+f"(d[0]), "+f"(d[1]), "+f"(d[2]), "+f"(d[3])
        : "r"(a0), "r"(a1), "r"(a2), "r"(a3), "r"(b0), "r"(b1));
}
// .cg: L2-only — weight tiles are L2-resident and shared by all CTAs.
#define CP_ASYNC16_CG(dst, src) \
    asm volatile("cp.async.cg.shared.global [%0], [%1], 16;" :: "r"(dst), "l"(src))
#define CP_COMMIT() asm volatile("cp.async.commit_group;" ::: "memory")
#define CP_WAIT0() asm volatile("cp.async.wait_group 0;" ::: "memory")

__device__ __forceinline__ uint32_t pk2h(float a, float b) {
    __half2 h = __floats2half2_rn(a, b);
    return *(uint32_t*)&h;
}

// ======================= fp16 B-split warp-MMA GEMM (R11, proven) ============
#define ASTR 40
#define AH_OFF 0
#define BH_OFF 5120
#define BL_OFF 10240
#define BUF_ELE 15360
#define GEMM_SMEM (2 * BUF_ELE * 2)

template <int NSEG, int RELU>
__global__ void __launch_bounds__(256, 2) mma_gemm(
    const __half* __restrict__ X, const __half* __restrict__ Agg,
    const __half* __restrict__ Wh, const __half* __restrict__ Wl,
    const float* __restrict__ bias, __half* __restrict__ C, int M) {
    extern __shared__ __half sm[];
    const int KTOT = NSEG * 128;
    const int CHUNKS = NSEG * 4;
    int tid = threadIdx.x, lane = tid & 31, wid = tid >> 5;
    int warpM = wid & 1, warpN = wid >> 1;
    int rowBlock = blockIdx.x * 128;
    uint32_t smb = smem_to_u32(sm);

    int arow = tid >> 1, ahalf = tid & 1;
    size_t grow = (size_t)(rowBlock + arow);

    float acc[4][4][4];
#pragma unroll
    for (int i = 0; i < 4; i++)
#pragma unroll
        for (int j = 0; j < 4; j++)
#pragma unroll
            for (int k = 0; k < 4; k++) acc[i][j][k] = 0.f;

    uint4 ar0, ar1;

    // ---- prologue: stage chunk 0 into buf 0 ----
    {
        const uint4* ap = (const uint4*)(X + grow * 128 + ahalf * 16);
        ar0 = ap[0]; ar1 = ap[1];
        const __half* wh = Wh + (size_t)arow * KTOT + ahalf * 16;
        const __half* wl = Wl + (size_t)arow * KTOT + ahalf * 16;
        uint32_t dH = smb + (uint32_t)(BH_OFF + arow * ASTR + ahalf * 16) * 2;
        uint32_t dL = smb + (uint32_t)(BL_OFF + arow * ASTR + ahalf * 16) * 2;
        CP_ASYNC16_CG(dH, wh); CP_ASYNC16_CG(dH + 16, wh + 8);
        CP_ASYNC16_CG(dL, wl); CP_ASYNC16_CG(dL + 16, wl + 8);
        CP_COMMIT();
        uint4* dst = (uint4*)(sm + AH_OFF + arow * ASTR + ahalf * 16);
        dst[0] = ar0; dst[1] = ar1;
    }
    CP_WAIT0();
    __syncthreads();

    int lr8 = lane & 7, lb = lane >> 3;
    int bRowL = ((lane >> 4) << 3) + lr8;     // 0..15
    int bColL = ((lane >> 3) & 1) * 8;        // 0 or 8

    for (int c = 0; c < CHUNKS; c++) {
        int buf = c & 1;
        uint32_t base = smb + (uint32_t)buf * BUF_ELE * 2;
        bool hasNext = (c + 1) < CHUNKS;

        if (hasNext) {
            int cn = c + 1;
            int seg = cn >> 2, kin = (cn & 3) * 32;
            const __half* wh = Wh + (size_t)arow * KTOT + cn * 32 + ahalf * 16;
            const __half* wl = Wl + (size_t)arow * KTOT + cn * 32 + ahalf * 16;
            uint32_t off = (uint32_t)((buf ^ 1) * BUF_ELE) * 2;
            uint32_t dH = smb + off + (uint32_t)(BH_OFF + arow * ASTR + ahalf * 16) * 2;
            uint32_t dL = smb + off + (uint32_t)(BL_OFF + arow * ASTR + ahalf * 16) * 2;
            CP_ASYNC16_CG(dH, wh); CP_ASYNC16_CG(dH + 16, wh + 8);
            CP_ASYNC16_CG(dL, wl); CP_ASYNC16_CG(dL + 16, wl + 8);
            CP_COMMIT();
            const __half* As = (NSEG == 1 || seg == 0) ? X : Agg + (size_t)(seg - 1) * NN * 128;
            const uint4* ap = (const uint4*)(As + grow * 128 + kin + ahalf * 16);
            ar0 = ap[0]; ar1 = ap[1];
        }

        // ---- MMA on current buffer ----
        {
            uint32_t aH = base + AH_OFF * 2;
            uint32_t bH = base + BH_OFF * 2, bL = base + BL_OFF * 2;
#pragma unroll
            for (int ks = 0; ks < 2; ks++) {
                uint32_t bhf[4][2], blf[4][2];
#pragma unroll
                for (int p = 0; p < 2; p++) {
                    int bRow = warpN * 32 + p * 16 + bRowL;
                    uint32_t o = (uint32_t)(bRow * ASTR + ks * 16 + bColL) * 2;
                    ldsm_x4(bhf[2 * p][0], bhf[2 * p][1], bhf[2 * p + 1][0],
                            bhf[2 * p + 1][1], bH + o);
                    ldsm_x4(blf[2 * p][0], blf[2 * p][1], blf[2 * p + 1][0],
                            blf[2 * p + 1][1], bL + o);
                }
                int aCol = ks * 16 + (lb >> 1) * 8;
#pragma unroll
                for (int mi = 0; mi < 4; mi++) {
                    int aRow = warpM * 64 + mi * 16 + (lb & 1) * 8 + lr8;
                    uint32_t o = (uint32_t)(aRow * ASTR + aCol) * 2;
                    uint32_t a0, a1, a2, a3;
                    ldsm_x4(a0, a1, a2, a3, aH + o);
#pragma unroll
                    for (int ni = 0; ni < 4; ni++) {
                        mma16816(acc[mi][ni], a0, a1, a2, a3, bhf[ni][0], bhf[ni][1]);
                        mma16816(acc[mi][ni], a0, a1, a2, a3, blf[ni][0], blf[ni][1]);
                    }
                }
            }
        }

        if (hasNext) {
            uint4* dst = (uint4*)(sm + (buf ^ 1) * BUF_ELE + AH_OFF + arow * ASTR + ahalf * 16);
            dst[0] = ar0; dst[1] = ar1;
        }
        CP_WAIT0();
        __syncthreads();
    }

    // ---- epilogue: bias + act, round to fp16 plane (bias hoisted) ----
    int gid = lane >> 2, qid = lane & 3;
    float bx[4][2];
#pragma unroll
    for (int ni = 0; ni < 4; ni++) {
        int cb = warpN * 32 + ni * 8 + qid * 2;
        bx[ni][0] = bias[cb];
        bx[ni][1] = bias[cb + 1];
    }
#pragma unroll
    for (int mi = 0; mi < 4; mi++) {
        int r0 = rowBlock + warpM * 64 + mi * 16 + gid;
        int r1 = r0 + 8;
#pragma unroll
        for (int ni = 0; ni < 4; ni++) {
            int cb = warpN * 32 + ni * 8 + qid * 2;
            float v0 = acc[mi][ni][0] + bx[ni][0], v1 = acc[mi][ni][1] + bx[ni][1];
            float v2 = acc[mi][ni][2] + bx[ni][0], v3 = acc[mi][ni][3] + bx[ni][1];
            if (RELU) { v0 = lrelu(v0); v1 = lrelu(v1); v2 = lrelu(v2); v3 = lrelu(v3); }
            if (r0 < M) *(uint32_t*)(C + (size_t)r0 * 128 + cb) = pk2h(v0, v1);
            if (r1 < M) *(uint32_t*)(C + (size_t)r1 * 128 + cb) = pk2h(v2, v3);
        }
    }
}

// ======================= feature packing (vectorized) ========================
// one thread per (row, 4-col group): float4 loads for des/tweet, uint2 stores
__global__ void pack_kernel(const float* __restrict__ des, const float* __restrict__ tweet,
                            const float* __restrict__ nump, const float* __restrict__ catp,
                            __half* __restrict__ P) {
    long idx = blockIdx.x * 256L + threadIdx.x;
    if (idx >= (long)NN * 32) return;
    int row = (int)(idx >> 5), g = (int)(idx & 31);
    float4 v = make_float4(0.f, 0.f, 0.f, 0.f);
    if (row < NU) {
        if (g < 25) {
            v = *(const float4*)(des + (size_t)row * 100 + g * 4);
        } else if (g < 30) {
            float t[4];
#pragma unroll
            for (int j = 0; j < 4; j++) {
                int col = g * 4 + j;
                if (col < 106) t[j] = nump[(size_t)row * 6 + (col - 100)];
                else if (col < 117) t[j] = catp[(size_t)row * 11 + (col - 106)];
                else t[j] = 0.f;
            }
            v = make_float4(t[0], t[1], t[2], t[3]);
        }
    } else {
        if (g < 25) v = *(const float4*)(tweet + (size_t)(row - NU) * 100 + g * 4);
    }
    uint2 o = make_uint2(pk2h(v.x, v.y), pk2h(v.z, v.w));
    *(uint2*)(P + (size_t)row * 128 + g * 4) = o;
}

// ======================= weight pre-conversion (hi/lo split) =================
__global__ void prep_W_kernel(const float* __restrict__ Wd, const float* __restrict__ bd,
                              const float* __restrict__ Wn, const float* __restrict__ bn,
                              const float* __restrict__ Wc, const float* __restrict__ bc,
                              const float* __restrict__ Wt, const float* __restrict__ Win,
                              const float* __restrict__ root, const float* __restrict__ rw,
                              const float* __restrict__ Wo1) {
    int idx = blockIdx.x * 256 + threadIdx.x;
    if (idx >= BTOT + 128) return;
    if (idx >= BTOT) {
        int n = idx - BTOT;
        g_biasU[n] = (n < 64) ? bd[n] : (n < 96) ? bn[n - 64] : bc[n - 96];
        return;
    }
    float v = 0.f;
    if (idx < 16384) {  // featU blockdiag [n,k=128]
        int n = idx >> 7, k = idx & 127;
        if (n < 64) { if (k < 100) v = Wd[n * 100 + k]; }
        else if (n < 96) { if (k >= 100 && k < 106) v = Wn[(n - 64) * 6 + (k - 100)]; }
        else { if (k >= 106 && k < 117) v = Wc[(n - 96) * 11 + (k - 106)]; }
    } else if (idx < 32768) {  // featT
        int l = idx - 16384;
        int n = l >> 7, k = l & 127;
        if (k < 100) v = Wt[n * 100 + k];
    } else if (idx < 49152) {  // lin
        v = Win[idx - 32768];
    } else if (idx < 98304) {  // conv: [n, k=384]: seg0 root^T, seg1/2 rw^T
        int l = idx - 49152;
        int n = l / 384, k = l % 384;
        if (k < 128) v = root[k * 128 + n];
        else if (k < 256) v = rw[(k - 128) * 128 + n];
        else v = rw[16384 + (k - 256) * 128 + n];
    } else {  // o1
        v = Wo1[idx - 98304];
    }
    __half h = __float2half_rn(v);
    g_Wh[idx] = h;
    g_Wl[idx] = __float2half_rn(v - __half2float(h));
}

// ======================= CSR build =======================
__global__ void zero2_kernel(int* __restrict__ a, int* __restrict__ b, int n) {
    int i = blockIdx.x * 256 + threadIdx.x;
    if (i < n) { a[i] = 0; b[i] = 0; }
}

__global__ void count_kernel(const int* __restrict__ ei, const int* __restrict__ et,
                             int* __restrict__ cnt) {
    int e = blockIdx.x * 256 + threadIdx.x;
    if (e >= NE) return;
    atomicAdd(&cnt[et[e] * NN + ei[NE + e]], 1);
}

#define SCAN_BS 512
__global__ void scan1_kernel(const int* __restrict__ cnt, int* __restrict__ off,
                             int* __restrict__ bsum, int n) {
    __shared__ int sh[SCAN_BS];
    int t = threadIdx.x;
    int i = blockIdx.x * SCAN_BS + t;
    int v = (i < n) ? cnt[i] : 0;
    sh[t] = v;
    __syncthreads();
#pragma unroll
    for (int d = 1; d < SCAN_BS; d <<= 1) {
        int x = (t >= d) ? sh[t - d] : 0;
        __syncthreads();
        sh[t] += x;
        __syncthreads();
    }
    if (i < n) off[i] = sh[t] - v;
    if (t == SCAN_BS - 1) bsum[blockIdx.x] = sh[t];
}

__global__ void scan2_kernel(int* __restrict__ bsum, int nb) {
    __shared__ int sh[1024];
    int t = threadIdx.x;
    int v = (t < nb) ? bsum[t] : 0;
    sh[t] = v;
    __syncthreads();
#pragma unroll
    for (int d = 1; d < 1024; d <<= 1) {
        int x = (t >= d) ? sh[t - d] : 0;
        __syncthreads();
        sh[t] += x;
        __syncthreads();
    }
    if (t < nb) bsum[t] = sh[t] - v;
}

__global__ void scan3_kernel(int* __restrict__ off, const int* __restrict__ bsum, int n) {
    int i = blockIdx.x * SCAN_BS + threadIdx.x;
    if (i < n) off[i] += bsum[blockIdx.x];
}

__global__ void fill_kernel(const int* __restrict__ ei, const int* __restrict__ et,
                            const int* __restrict__ off, int* __restrict__ cur,
                            int* __restrict__ esrc) {
    int e = blockIdx.x * 256 + threadIdx.x;
    if (e >= NE) return;
    int slot = et[e] * NN + ei[NE + e];
    int pos = off[slot] + atomicAdd(&cur[slot], 1);
    esrc[pos] = ei[e];
}

// ======================= CSR gather-mean aggregation (fp16 plane) ============
__global__ void agg_kernel(const __half* __restrict__ X, const int* __restrict__ off,
                           const int* __restrict__ cnt, const int* __restrict__ esrc,
                           __half* __restrict__ Agg) {
    int w = (blockIdx.x * blockDim.x + threadIdx.x) >> 5;
    int lane = threadIdx.x & 31;
    if (w >= NSLOT) return;
    int beg = off[w], deg = cnt[w];
    float4 acc = make_float4(0.f, 0.f, 0.f, 0.f);
    for (int i = 0; i < deg; i++) {
        int src = __ldg(&esrc[beg + i]);
        uint2 hu = *(const uint2*)(X + (size_t)src * 128 + lane * 4);
        float2 h0 = __half22float2(*(__half2*)&hu.x), h1 = __half22float2(*(__half2*)&hu.y);
        acc.x += h0.x; acc.y += h0.y; acc.z += h1.x; acc.w += h1.y;
    }
    float s = (deg > 0) ? 1.f / (float)deg : 0.f;
    uint2 o = make_uint2(pk2h(acc.x * s, acc.y * s), pk2h(acc.z * s, acc.w * s));
    *(uint2*)(Agg + (size_t)w * 128 + lane * 4) = o;
}

// ======================= final 128->2 projection =======================
__global__ void out_kernel(const __half* __restrict__ X, const float* __restrict__ W2,
                           const float* __restrict__ b2, float* __restrict__ out) {
    int gw = (blockIdx.x * blockDim.x + threadIdx.x) >> 5;
    int lane = threadIdx.x & 31;
    if (gw >= NN) return;
    uint2 hu = *(const uint2*)(X + (size_t)gw * 128 + lane * 4);
    float2 h0 = __half22float2(*(__half2*)&hu.x), h1 = __half22float2(*(__half2*)&hu.y);
    float4 w0 = *(const float4*)(W2 + lane * 4);
    float4 w1 = *(const float4*)(W2 + 128 + lane * 4);
    float s0 = h0.x * w0.x + h0.y * w0.y + h1.x * w0.z + h1.y * w0.w;
    float s1 = h0.x * w1.x + h0.y * w1.y + h1.x * w1.z + h1.y * w1.w;
#pragma unroll
    for (int off = 16; off; off >>= 1) {
        s0 += __shfl_xor_sync(0xffffffffu, s0, off);
        s1 += __shfl_xor_sync(0xffffffffu, s1, off);
    }
    if (lane == 0) {
        out[(size_t)gw * 2 + 0] = s0 + b2[0];
        out[(size_t)gw * 2 + 1] = s1 + b2[1];
    }
}

// ---------------------------------------------------------------------------
extern "C" void kernel_launch(void* const* d_in, const int* in_sizes, int n_in,
                              void* d_out, int out_size) {
    const float* des   = (const float*)d_in[0];
    const float* tweet = (const float*)d_in[1];
    const float* nump  = (const float*)d_in[2];
    const float* catp  = (const float*)d_in[3];
    const int*   ei    = (const int*)d_in[4];
    const int*   et    = (const int*)d_in[5];
    const float* Wd  = (const float*)d_in[6];  const float* bd  = (const float*)d_in[7];
    const float* Wn  = (const float*)d_in[8];  const float* bn  = (const float*)d_in[9];
    const float* Wc  = (const float*)d_in[10]; const float* bc  = (const float*)d_in[11];
    const float* Wt  = (const float*)d_in[12]; const float* bt  = (const float*)d_in[13];
    const float* Win = (const float*)d_in[14]; const float* bin = (const float*)d_in[15];
    const float* rw    = (const float*)d_in[16];
    const float* rroot = (const float*)d_in[17];
    const float* rbias = (const float*)d_in[18];
    const float* Wo1 = (const float*)d_in[19]; const float* bo1 = (const float*)d_in[20];
    const float* Wo2 = (const float*)d_in[21]; const float* bo2 = (const float*)d_in[22];
    float* out = (float*)d_out;

    __half *pX1, *pX2, *pG, *pWh, *pWl;
    float* pBiasU;
    int *pCnt, *pOff, *pCur, *pBsum, *pEsrc;
    cudaGetSymbolAddress((void**)&pX1, g_X1);
    cudaGetSymbolAddress((void**)&pX2, g_X2);
    cudaGetSymbolAddress((void**)&pG, g_agg);
    cudaGetSymbolAddress((void**)&pWh, g_Wh);
    cudaGetSymbolAddress((void**)&pWl, g_Wl);
    cudaGetSymbolAddress((void**)&pBiasU, g_biasU);
    cudaGetSymbolAddress((void**)&pCnt, g_cnt);
    cudaGetSymbolAddress((void**)&pOff, g_off);
    cudaGetSymbolAddress((void**)&pCur, g_cur);
    cudaGetSymbolAddress((void**)&pBsum, g_bsum);
    cudaGetSymbolAddress((void**)&pEsrc, g_esrc);

    cudaFuncSetAttribute(mma_gemm<1, 1>, cudaFuncAttributeMaxDynamicSharedMemorySize, GEMM_SMEM);
    cudaFuncSetAttribute(mma_gemm<3, 0>, cudaFuncAttributeMaxDynamicSharedMemorySize, GEMM_SMEM);

    // side stream for CSR build overlap (created once, on the uncaptured
    // correctness call; capture uses fork/join events — supported pattern)
    static cudaStream_t sB = nullptr;
    static cudaEvent_t evFork = nullptr, evJoin = nullptr;
    if (sB == nullptr) {
        cudaStreamCreateWithFlags(&sB, cudaStreamNonBlocking);
        cudaEventCreateWithFlags(&evFork, cudaEventDisableTiming);
        cudaEventCreateWithFlags(&evJoin, cudaEventDisableTiming);
    }

    const int GU = (NU + 127) / 128;   // 782
    const int GN = (NN + 127) / 128;   // 1563
    const int SCAN_NB = (NSLOT + SCAN_BS - 1) / SCAN_BS;

    // ---- fork: CSR build chain on side stream (depends only on ei/et) ----
    cudaEventRecord(evFork, 0);
    cudaStreamWaitEvent(sB, evFork, 0);
    zero2_kernel<<<(NSLOT + 255) / 256, 256, 0, sB>>>(pCnt, pCur, NSLOT);
    count_kernel<<<(NE + 255) / 256, 256, 0, sB>>>(ei, et, pCnt);
    scan1_kernel<<<SCAN_NB, SCAN_BS, 0, sB>>>(pCnt, pOff, pBsum, NSLOT);
    scan2_kernel<<<1, 1024, 0, sB>>>(pBsum, SCAN_NB);
    scan3_kernel<<<SCAN_NB, SCAN_BS, 0, sB>>>(pOff, pBsum, NSLOT);
    fill_kernel<<<(NE + 255) / 256, 256, 0, sB>>>(ei, et, pOff, pCur, pEsrc);
    cudaEventRecord(evJoin, sB);

    // ---- main stream: pack -> weights -> feat GEMMs -> lin ----
    pack_kernel<<<(NN * 32 + 255) / 256, 256>>>(des, tweet, nump, catp, pX2);
    prep_W_kernel<<<(BTOT + 128 + 255) / 256, 256>>>(Wd, bd, Wn, bn, Wc, bc, Wt, Win,
                                                     rroot, rw, Wo1);
    mma_gemm<1, 1><<<GU, 256, GEMM_SMEM>>>(pX2, nullptr, pWh, pWl, pBiasU, pX1, NU);
    mma_gemm<1, 1><<<GU, 256, GEMM_SMEM>>>(pX2 + (size_t)NU * 128, nullptr,
                                           pWh + 16384, pWl + 16384, bt,
                                           pX1 + (size_t)NU * 128, NU);
    mma_gemm<1, 1><<<GN, 256, GEMM_SMEM>>>(pX1, nullptr, pWh + 32768, pWl + 32768,
                                           bin, pX2, NN);

    // ---- join: CSR must be complete before aggregation ----
    cudaStreamWaitEvent(0, evJoin, 0);

    // conv1: X2 -> X1
    agg_kernel<<<NSLOT / 8, 256>>>(pX2, pOff, pCnt, pEsrc, pG);
    mma_gemm<3, 0><<<GN, 256, GEMM_SMEM>>>(pX2, pG, pWh + 49152, pWl + 49152,
                                           rbias, pX1, NN);
    // conv2: X1 -> X2
    agg_kernel<<<NSLOT / 8, 256>>>(pX1, pOff, pCnt, pEsrc, pG);
    mma_gemm<3, 0><<<GN, 256, GEMM_SMEM>>>(pX1, pG, pWh + 49152, pWl + 49152,
                                           rbias, pX2, NN);
    // o1: X2 -> X1
    mma_gemm<1, 1><<<GN, 256, GEMM_SMEM>>>(pX2, nullptr, pWh + 98304, pWl + 98304,
                                           bo1, pX1, NN);
    // out = x @ W_o2^T + b_o2
    out_kernel<<<NN / 8, 256>>>(pX1, Wo2, bo2, out);
}

// round 16
// speedup vs baseline: 1.1374x; 1.0484x over previous
#include <cuda_runtime.h>
#include <cuda_fp16.h>
#include <cstdint>

#define NU 100000
#define NT 100000
#define NN 200000
#define NE 600000
#define NSLOT (2 * NN)
#define NPAD (NN + 192)          // row padding: tail CTAs may read past M

// ---- scratch (device globals; no runtime allocation) ----
__device__ __align__(16) __half g_X1[(size_t)NPAD * 128];
__device__ __align__(16) __half g_X2[(size_t)NPAD * 128];
__device__ __align__(16) __half g_agg[(size_t)(NSLOT + 192) * 128];
__device__ float g_part[(size_t)4 * NN * 2];   // fused-out partials [warpN][row][2]
// CSR structures
__device__ int g_cnt[NSLOT];
__device__ int g_off[NSLOT];
__device__ int g_cur[NSLOT];
__device__ int g_bsum[1024];
__device__ int g_esrc[NE];
// pre-converted weights, fp16 hi/lo planes, [N=128, Ktot] K-major rows:
// featU @0 (Ktot128), featT @16384, lin @32768, conv @49152 (Ktot384), o1 @98304
#define BTOT 114688
__device__ __align__(16) __half g_Wh[BTOT];
__device__ __align__(16) __half g_Wl[BTOT];
__device__ float g_biasU[128];

__device__ __forceinline__ float lrelu(float x) { return x > 0.f ? x : 0.01f * x; }

// ======================= PTX helpers (portable sm_80+) =======================
__device__ __forceinline__ uint32_t smem_to_u32(const void* p) {
    uint32_t a;
    asm("{ .reg .u64 t; cvta.to.shared.u64 t, %1; cvt.u32.u64 %0, t; }" : "=r"(a) : "l"(p));
    return a;
}
__device__ __forceinline__ void ldsm_x4(uint32_t& r0, uint32_t& r1, uint32_t& r2,
                                        uint32_t& r3, uint32_t a) {
    asm volatile("ldmatrix.sync.aligned.m8n8.x4.shared.b16 {%0,%1,%2,%3}, [%4];"
                 : "=r"(r0), "=r"(r1), "=r"(r2), "=r"(r3) : "r"(a));
}
__device__ __forceinline__ void mma16816(float* d, uint32_t a0, uint32_t a1, uint32_t a2,
                                         uint32_t a3, uint32_t b0, uint32_t b1) {
    asm volatile(
        "mma.sync.aligned.m16n8k16.row.col.f32.f16.f16.f32 "
        "{%0,%1,%2,%3}, {%4,%5,%6,%7}, {%8,%9}, {%0,%1,%2,%3};"
        : "+f"(d[0]), "+f"(d[1]), "+f"(d[2]), "+f"(d[3])
        : "r"(a0), "r"(a1), "r"(a2), "r"(a3), "r"(b0), "r"(b1));
}
// .cg: L2-only — weight tiles are L2-resident and shared by all CTAs.
#define CP_ASYNC16_CG(dst, src) \
    asm volatile("cp.async.cg.shared.global [%0], [%1], 16;" :: "r"(dst), "l"(src))
#define CP_COMMIT() asm volatile("cp.async.commit_group;" ::: "memory")
#define CP_WAIT0() asm volatile("cp.async.wait_group 0;" ::: "memory")

__device__ __forceinline__ uint32_t pk2h(float a, float b) {
    __half2 h = __floats2half2_rn(a, b);
    return *(uint32_t*)&h;
}

// ======================= fp16 B-split warp-MMA GEMM (R11 core) ===============
// FUSE=1 (o1 layer): instead of storing C, dot lrelu(C) rows against the two
// Wo2 rows, shfl-reduce over qid lanes, write per-warpN partials (no atomics).
#define ASTR 40
#define AH_OFF 0
#define BH_OFF 5120
#define BL_OFF 10240
#define BUF_ELE 15360
#define GEMM_SMEM (2 * BUF_ELE * 2)

template <int NSEG, int RELU, int FUSE>
__global__ void __launch_bounds__(256, 2) mma_gemm(
    const __half* __restrict__ X, const __half* __restrict__ Agg,
    const __half* __restrict__ Wh, const __half* __restrict__ Wl,
    const float* __restrict__ bias, __half* __restrict__ C,
    const float* __restrict__ W2, float* __restrict__ part, int M) {
    extern __shared__ __half sm[];
    const int KTOT = NSEG * 128;
    const int CHUNKS = NSEG * 4;
    int tid = threadIdx.x, lane = tid & 31, wid = tid >> 5;
    int warpM = wid & 1, warpN = wid >> 1;
    int rowBlock = blockIdx.x * 128;
    uint32_t smb = smem_to_u32(sm);

    int arow = tid >> 1, ahalf = tid & 1;
    size_t grow = (size_t)(rowBlock + arow);

    float acc[4][4][4];
#pragma unroll
    for (int i = 0; i < 4; i++)
#pragma unroll
        for (int j = 0; j < 4; j++)
#pragma unroll
            for (int k = 0; k < 4; k++) acc[i][j][k] = 0.f;

    uint4 ar0, ar1;

    // ---- prologue: stage chunk 0 into buf 0 ----
    {
        const uint4* ap = (const uint4*)(X + grow * 128 + ahalf * 16);
        ar0 = ap[0]; ar1 = ap[1];
        const __half* wh = Wh + (size_t)arow * KTOT + ahalf * 16;
        const __half* wl = Wl + (size_t)arow * KTOT + ahalf * 16;
        uint32_t dH = smb + (uint32_t)(BH_OFF + arow * ASTR + ahalf * 16) * 2;
        uint32_t dL = smb + (uint32_t)(BL_OFF + arow * ASTR + ahalf * 16) * 2;
        CP_ASYNC16_CG(dH, wh); CP_ASYNC16_CG(dH + 16, wh + 8);
        CP_ASYNC16_CG(dL, wl); CP_ASYNC16_CG(dL + 16, wl + 8);
        CP_COMMIT();
        uint4* dst = (uint4*)(sm + AH_OFF + arow * ASTR + ahalf * 16);
        dst[0] = ar0; dst[1] = ar1;
    }
    CP_WAIT0();
    __syncthreads();

    int lr8 = lane & 7, lb = lane >> 3;
    int bRowL = ((lane >> 4) << 3) + lr8;     // 0..15
    int bColL = ((lane >> 3) & 1) * 8;        // 0 or 8

    for (int c = 0; c < CHUNKS; c++) {
        int buf = c & 1;
        uint32_t base = smb + (uint32_t)buf * BUF_ELE * 2;
        bool hasNext = (c + 1) < CHUNKS;

        if (hasNext) {
            int cn = c + 1;
            int seg = cn >> 2, kin = (cn & 3) * 32;
            const __half* wh = Wh + (size_t)arow * KTOT + cn * 32 + ahalf * 16;
            const __half* wl = Wl + (size_t)arow * KTOT + cn * 32 + ahalf * 16;
            uint32_t off = (uint32_t)((buf ^ 1) * BUF_ELE) * 2;
            uint32_t dH = smb + off + (uint32_t)(BH_OFF + arow * ASTR + ahalf * 16) * 2;
            uint32_t dL = smb + off + (uint32_t)(BL_OFF + arow * ASTR + ahalf * 16) * 2;
            CP_ASYNC16_CG(dH, wh); CP_ASYNC16_CG(dH + 16, wh + 8);
            CP_ASYNC16_CG(dL, wl); CP_ASYNC16_CG(dL + 16, wl + 8);
            CP_COMMIT();
            const __half* As = (NSEG == 1 || seg == 0) ? X : Agg + (size_t)(seg - 1) * NN * 128;
            const uint4* ap = (const uint4*)(As + grow * 128 + kin + ahalf * 16);
            ar0 = ap[0]; ar1 = ap[1];
        }

        // ---- MMA on current buffer ----
        {
            uint32_t aH = base + AH_OFF * 2;
            uint32_t bH = base + BH_OFF * 2, bL = base + BL_OFF * 2;
#pragma unroll
            for (int ks = 0; ks < 2; ks++) {
                uint32_t bhf[4][2], blf[4][2];
#pragma unroll
                for (int p = 0; p < 2; p++) {
                    int bRow = warpN * 32 + p * 16 + bRowL;
                    uint32_t o = (uint32_t)(bRow * ASTR + ks * 16 + bColL) * 2;
                    ldsm_x4(bhf[2 * p][0], bhf[2 * p][1], bhf[2 * p + 1][0],
                            bhf[2 * p + 1][1], bH + o);
                    ldsm_x4(blf[2 * p][0], blf[2 * p][1], blf[2 * p + 1][0],
                            blf[2 * p + 1][1], bL + o);
                }
                int aCol = ks * 16 + (lb >> 1) * 8;
#pragma unroll
                for (int mi = 0; mi < 4; mi++) {
                    int aRow = warpM * 64 + mi * 16 + (lb & 1) * 8 + lr8;
                    uint32_t o = (uint32_t)(aRow * ASTR + aCol) * 2;
                    uint32_t a0, a1, a2, a3;
                    ldsm_x4(a0, a1, a2, a3, aH + o);
#pragma unroll
                    for (int ni = 0; ni < 4; ni++) {
                        mma16816(acc[mi][ni], a0, a1, a2, a3, bhf[ni][0], bhf[ni][1]);
                        mma16816(acc[mi][ni], a0, a1, a2, a3, blf[ni][0], blf[ni][1]);
                    }
                }
            }
        }

        if (hasNext) {
            uint4* dst = (uint4*)(sm + (buf ^ 1) * BUF_ELE + AH_OFF + arow * ASTR + ahalf * 16);
            dst[0] = ar0; dst[1] = ar1;
        }
        CP_WAIT0();
        __syncthreads();
    }

    // ---- epilogue ----
    int gid = lane >> 2, qid = lane & 3;
    float bx[4][2];
#pragma unroll
    for (int ni = 0; ni < 4; ni++) {
        int cb = warpN * 32 + ni * 8 + qid * 2;
        bx[ni][0] = bias[cb];
        bx[ni][1] = bias[cb + 1];
    }

    if (FUSE) {
        // fused 128->2 projection: out_row = lrelu(C_row) . W2[0/1]
        float w2a[4][2], w2b[4][2];
#pragma unroll
        for (int ni = 0; ni < 4; ni++) {
            int cb = warpN * 32 + ni * 8 + qid * 2;
            w2a[ni][0] = W2[cb];       w2a[ni][1] = W2[cb + 1];
            w2b[ni][0] = W2[128 + cb]; w2b[ni][1] = W2[128 + cb + 1];
        }
#pragma unroll
        for (int mi = 0; mi < 4; mi++) {
            float s00 = 0.f, s01 = 0.f, s10 = 0.f, s11 = 0.f;
#pragma unroll
            for (int ni = 0; ni < 4; ni++) {
                float v0 = lrelu(acc[mi][ni][0] + bx[ni][0]);
                float v1 = lrelu(acc[mi][ni][1] + bx[ni][1]);
                float v2 = lrelu(acc[mi][ni][2] + bx[ni][0]);
                float v3 = lrelu(acc[mi][ni][3] + bx[ni][1]);
                s00 += v0 * w2a[ni][0] + v1 * w2a[ni][1];
                s01 += v0 * w2b[ni][0] + v1 * w2b[ni][1];
                s10 += v2 * w2a[ni][0] + v3 * w2a[ni][1];
                s11 += v2 * w2b[ni][0] + v3 * w2b[ni][1];
            }
#pragma unroll
            for (int o = 1; o < 4; o <<= 1) {
                s00 += __shfl_xor_sync(0xffffffffu, s00, o);
                s01 += __shfl_xor_sync(0xffffffffu, s01, o);
                s10 += __shfl_xor_sync(0xffffffffu, s10, o);
                s11 += __shfl_xor_sync(0xffffffffu, s11, o);
            }
            if (qid == 0) {
                int r0 = rowBlock + warpM * 64 + mi * 16 + gid;
                int r1 = r0 + 8;
                if (r0 < M) {
                    float2 t = make_float2(s00, s01);
                    *(float2*)(part + ((size_t)warpN * NN + r0) * 2) = t;
                }
                if (r1 < M) {
                    float2 t = make_float2(s10, s11);
                    *(float2*)(part + ((size_t)warpN * NN + r1) * 2) = t;
                }
            }
        }
    } else {
#pragma unroll
        for (int mi = 0; mi < 4; mi++) {
            int r0 = rowBlock + warpM * 64 + mi * 16 + gid;
            int r1 = r0 + 8;
#pragma unroll
            for (int ni = 0; ni < 4; ni++) {
                int cb = warpN * 32 + ni * 8 + qid * 2;
                float v0 = acc[mi][ni][0] + bx[ni][0], v1 = acc[mi][ni][1] + bx[ni][1];
                float v2 = acc[mi][ni][2] + bx[ni][0], v3 = acc[mi][ni][3] + bx[ni][1];
                if (RELU) { v0 = lrelu(v0); v1 = lrelu(v1); v2 = lrelu(v2); v3 = lrelu(v3); }
                if (r0 < M) *(uint32_t*)(C + (size_t)r0 * 128 + cb) = pk2h(v0, v1);
                if (r1 < M) *(uint32_t*)(C + (size_t)r1 * 128 + cb) = pk2h(v2, v3);
            }
        }
    }
}

// ======================= partial reduce for fused out ========================
__global__ void reduce_out_kernel(const float* __restrict__ part,
                                  const float* __restrict__ b2,
                                  float* __restrict__ out) {
    int i = blockIdx.x * 256 + threadIdx.x;
    if (i >= NN * 2) return;
    int r = i >> 1, c = i & 1;
    float s = b2[c];
#pragma unroll
    for (int w = 0; w < 4; w++) s += part[((size_t)w * NN + r) * 2 + c];
    out[i] = s;
}

// ======================= feature packing (vectorized) ========================
__global__ void pack_kernel(const float* __restrict__ des, const float* __restrict__ tweet,
                            const float* __restrict__ nump, const float* __restrict__ catp,
                            __half* __restrict__ P) {
    long idx = blockIdx.x * 256L + threadIdx.x;
    if (idx >= (long)NN * 32) return;
    int row = (int)(idx >> 5), g = (int)(idx & 31);
    float4 v = make_float4(0.f, 0.f, 0.f, 0.f);
    if (row < NU) {
        if (g < 25) {
            v = *(const float4*)(des + (size_t)row * 100 + g * 4);
        } else if (g < 30) {
            float t[4];
#pragma unroll
            for (int j = 0; j < 4; j++) {
                int col = g * 4 + j;
                if (col < 106) t[j] = nump[(size_t)row * 6 + (col - 100)];
                else if (col < 117) t[j] = catp[(size_t)row * 11 + (col - 106)];
                else t[j] = 0.f;
            }
            v = make_float4(t[0], t[1], t[2], t[3]);
        }
    } else {
        if (g < 25) v = *(const float4*)(tweet + (size_t)(row - NU) * 100 + g * 4);
    }
    uint2 o = make_uint2(pk2h(v.x, v.y), pk2h(v.z, v.w));
    *(uint2*)(P + (size_t)row * 128 + g * 4) = o;
}

// ======================= weight pre-conversion (hi/lo split) =================
__global__ void prep_W_kernel(const float* __restrict__ Wd, const float* __restrict__ bd,
                              const float* __restrict__ Wn, const float* __restrict__ bn,
                              const float* __restrict__ Wc, const float* __restrict__ bc,
                              const float* __restrict__ Wt, const float* __restrict__ Win,
                              const float* __restrict__ root, const float* __restrict__ rw,
                              const float* __restrict__ Wo1) {
    int idx = blockIdx.x * 256 + threadIdx.x;
    if (idx >= BTOT + 128) return;
    if (idx >= BTOT) {
        int n = idx - BTOT;
        g_biasU[n] = (n < 64) ? bd[n] : (n < 96) ? bn[n - 64] : bc[n - 96];
        return;
    }
    float v = 0.f;
    if (idx < 16384) {  // featU blockdiag [n,k=128]
        int n = idx >> 7, k = idx & 127;
        if (n < 64) { if (k < 100) v = Wd[n * 100 + k]; }
        else if (n < 96) { if (k >= 100 && k < 106) v = Wn[(n - 64) * 6 + (k - 100)]; }
        else { if (k >= 106 && k < 117) v = Wc[(n - 96) * 11 + (k - 106)]; }
    } else if (idx < 32768) {  // featT
        int l = idx - 16384;
        int n = l >> 7, k = l & 127;
        if (k < 100) v = Wt[n * 100 + k];
    } else if (idx < 49152) {  // lin
        v = Win[idx - 32768];
    } else if (idx < 98304) {  // conv: [n, k=384]: seg0 root^T, seg1/2 rw^T
        int l = idx - 49152;
        int n = l / 384, k = l % 384;
        if (k < 128) v = root[k * 128 + n];
        else if (k < 256) v = rw[(k - 128) * 128 + n];
        else v = rw[16384 + (k - 256) * 128 + n];
    } else {  // o1
        v = Wo1[idx - 98304];
    }
    __half h = __float2half_rn(v);
    g_Wh[idx] = h;
    g_Wl[idx] = __float2half_rn(v - __half2float(h));
}

// ======================= CSR build =======================
__global__ void zero2_kernel(int* __restrict__ a, int* __restrict__ b, int n) {
    int i = blockIdx.x * 256 + threadIdx.x;
    if (i < n) { a[i] = 0; b[i] = 0; }
}

__global__ void count_kernel(const int* __restrict__ ei, const int* __restrict__ et,
                             int* __restrict__ cnt) {
    int e = blockIdx.x * 256 + threadIdx.x;
    if (e >= NE) return;
    atomicAdd(&cnt[et[e] * NN + ei[NE + e]], 1);
}

#define SCAN_BS 512
__global__ void scan1_kernel(const int* __restrict__ cnt, int* __restrict__ off,
                             int* __restrict__ bsum, int n) {
    __shared__ int sh[SCAN_BS];
    int t = threadIdx.x;
    int i = blockIdx.x * SCAN_BS + t;
    int v = (i < n) ? cnt[i] : 0;
    sh[t] = v;
    __syncthreads();
#pragma unroll
    for (int d = 1; d < SCAN_BS; d <<= 1) {
        int x = (t >= d) ? sh[t - d] : 0;
        __syncthreads();
        sh[t] += x;
        __syncthreads();
    }
    if (i < n) off[i] = sh[t] - v;
    if (t == SCAN_BS - 1) bsum[blockIdx.x] = sh[t];
}

__global__ void scan2_kernel(int* __restrict__ bsum, int nb) {
    __shared__ int sh[1024];
    int t = threadIdx.x;
    int v = (t < nb) ? bsum[t] : 0;
    sh[t] = v;
    __syncthreads();
#pragma unroll
    for (int d = 1; d < 1024; d <<= 1) {
        int x = (t >= d) ? sh[t - d] : 0;
        __syncthreads();
        sh[t] += x;
        __syncthreads();
    }
    if (t < nb) bsum[t] = sh[t] - v;
}

__global__ void scan3_kernel(int* __restrict__ off, const int* __restrict__ bsum, int n) {
    int i = blockIdx.x * SCAN_BS + threadIdx.x;
    if (i < n) off[i] += bsum[blockIdx.x];
}

__global__ void fill_kernel(const int* __restrict__ ei, const int* __restrict__ et,
                            const int* __restrict__ off, int* __restrict__ cur,
                            int* __restrict__ esrc) {
    int e = blockIdx.x * 256 + threadIdx.x;
    if (e >= NE) return;
    int slot = et[e] * NN + ei[NE + e];
    int pos = off[slot] + atomicAdd(&cur[slot], 1);
    esrc[pos] = ei[e];
}

// ======================= CSR gather-mean aggregation (fp16 plane) ============
__global__ void agg_kernel(const __half* __restrict__ X, const int* __restrict__ off,
                           const int* __restrict__ cnt, const int* __restrict__ esrc,
                           __half* __restrict__ Agg) {
    int w = (blockIdx.x * blockDim.x + threadIdx.x) >> 5;
    int lane = threadIdx.x & 31;
    if (w >= NSLOT) return;
    int beg = off[w], deg = cnt[w];
    float4 acc = make_float4(0.f, 0.f, 0.f, 0.f);
    for (int i = 0; i < deg; i++) {
        int src = __ldg(&esrc[beg + i]);
        uint2 hu = *(const uint2*)(X + (size_t)src * 128 + lane * 4);
        float2 h0 = __half22float2(*(__half2*)&hu.x), h1 = __half22float2(*(__half2*)&hu.y);
        acc.x += h0.x; acc.y += h0.y; acc.z += h1.x; acc.w += h1.y;
    }
    float s = (deg > 0) ? 1.f / (float)deg : 0.f;
    uint2 o = make_uint2(pk2h(acc.x * s, acc.y * s), pk2h(acc.z * s, acc.w * s));
    *(uint2*)(Agg + (size_t)w * 128 + lane * 4) = o;
}

// ---------------------------------------------------------------------------
extern "C" void kernel_launch(void* const* d_in, const int* in_sizes, int n_in,
                              void* d_out, int out_size) {
    const float* des   = (const float*)d_in[0];
    const float* tweet = (const float*)d_in[1];
    const float* nump  = (const float*)d_in[2];
    const float* catp  = (const float*)d_in[3];
    const int*   ei    = (const int*)d_in[4];
    const int*   et    = (const int*)d_in[5];
    const float* Wd  = (const float*)d_in[6];  const float* bd  = (const float*)d_in[7];
    const float* Wn  = (const float*)d_in[8];  const float* bn  = (const float*)d_in[9];
    const float* Wc  = (const float*)d_in[10]; const float* bc  = (const float*)d_in[11];
    const float* Wt  = (const float*)d_in[12]; const float* bt  = (const float*)d_in[13];
    const float* Win = (const float*)d_in[14]; const float* bin = (const float*)d_in[15];
    const float* rw    = (const float*)d_in[16];
    const float* rroot = (const float*)d_in[17];
    const float* rbias = (const float*)d_in[18];
    const float* Wo1 = (const float*)d_in[19]; const float* bo1 = (const float*)d_in[20];
    const float* Wo2 = (const float*)d_in[21]; const float* bo2 = (const float*)d_in[22];
    float* out = (float*)d_out;

    __half *pX1, *pX2, *pG, *pWh, *pWl;
    float *pBiasU, *pPart;
    int *pCnt, *pOff, *pCur, *pBsum, *pEsrc;
    cudaGetSymbolAddress((void**)&pX1, g_X1);
    cudaGetSymbolAddress((void**)&pX2, g_X2);
    cudaGetSymbolAddress((void**)&pG, g_agg);
    cudaGetSymbolAddress((void**)&pWh, g_Wh);
    cudaGetSymbolAddress((void**)&pWl, g_Wl);
    cudaGetSymbolAddress((void**)&pBiasU, g_biasU);
    cudaGetSymbolAddress((void**)&pPart, g_part);
    cudaGetSymbolAddress((void**)&pCnt, g_cnt);
    cudaGetSymbolAddress((void**)&pOff, g_off);
    cudaGetSymbolAddress((void**)&pCur, g_cur);
    cudaGetSymbolAddress((void**)&pBsum, g_bsum);
    cudaGetSymbolAddress((void**)&pEsrc, g_esrc);

    cudaFuncSetAttribute(mma_gemm<1, 1, 0>, cudaFuncAttributeMaxDynamicSharedMemorySize, GEMM_SMEM);
    cudaFuncSetAttribute(mma_gemm<3, 0, 0>, cudaFuncAttributeMaxDynamicSharedMemorySize, GEMM_SMEM);
    cudaFuncSetAttribute(mma_gemm<1, 1, 1>, cudaFuncAttributeMaxDynamicSharedMemorySize, GEMM_SMEM);

    // side stream for CSR build overlap (created once, on the uncaptured
    // correctness call; capture uses fork/join events — supported pattern)
    static cudaStream_t sB = nullptr;
    static cudaEvent_t evFork = nullptr, evJoin = nullptr;
    if (sB == nullptr) {
        cudaStreamCreateWithFlags(&sB, cudaStreamNonBlocking);
        cudaEventCreateWithFlags(&evFork, cudaEventDisableTiming);
        cudaEventCreateWithFlags(&evJoin, cudaEventDisableTiming);
    }

    const int GU = (NU + 127) / 128;   // 782
    const int GN = (NN + 127) / 128;   // 1563
    const int SCAN_NB = (NSLOT + SCAN_BS - 1) / SCAN_BS;

    // ---- fork: CSR build chain on side stream (depends only on ei/et) ----
    cudaEventRecord(evFork, 0);
    cudaStreamWaitEvent(sB, evFork, 0);
    zero2_kernel<<<(NSLOT + 255) / 256, 256, 0, sB>>>(pCnt, pCur, NSLOT);
    count_kernel<<<(NE + 255) / 256, 256, 0, sB>>>(ei, et, pCnt);
    scan1_kernel<<<SCAN_NB, SCAN_BS, 0, sB>>>(pCnt, pOff, pBsum, NSLOT);
    scan2_kernel<<<1, 1024, 0, sB>>>(pBsum, SCAN_NB);
    scan3_kernel<<<SCAN_NB, SCAN_BS, 0, sB>>>(pOff, pBsum, NSLOT);
    fill_kernel<<<(NE + 255) / 256, 256, 0, sB>>>(ei, et, pOff, pCur, pEsrc);
    cudaEventRecord(evJoin, sB);

    // ---- main stream: pack -> weights -> feat GEMMs -> lin ----
    pack_kernel<<<(NN * 32 + 255) / 256, 256>>>(des, tweet, nump, catp, pX2);
    prep_W_kernel<<<(BTOT + 128 + 255) / 256, 256>>>(Wd, bd, Wn, bn, Wc, bc, Wt, Win,
                                                     rroot, rw, Wo1);
    mma_gemm<1, 1, 0><<<GU, 256, GEMM_SMEM>>>(pX2, nullptr, pWh, pWl, pBiasU, pX1,
                                              nullptr, nullptr, NU);
    mma_gemm<1, 1, 0><<<GU, 256, GEMM_SMEM>>>(pX2 + (size_t)NU * 128, nullptr,
                                              pWh + 16384, pWl + 16384, bt,
                                              pX1 + (size_t)NU * 128, nullptr, nullptr, NU);
    mma_gemm<1, 1, 0><<<GN, 256, GEMM_SMEM>>>(pX1, nullptr, pWh + 32768, pWl + 32768,
                                              bin, pX2, nullptr, nullptr, NN);

    // ---- join: CSR must be complete before aggregation ----
    cudaStreamWaitEvent(0, evJoin, 0);

    // conv1: X2 -> X1
    agg_kernel<<<NSLOT / 8, 256>>>(pX2, pOff, pCnt, pEsrc, pG);
    mma_gemm<3, 0, 0><<<GN, 256, GEMM_SMEM>>>(pX2, pG, pWh + 49152, pWl + 49152,
                                              rbias, pX1, nullptr, nullptr, NN);
    // conv2: X1 -> X2
    agg_kernel<<<NSLOT / 8, 256>>>(pX1, pOff, pCnt, pEsrc, pG);
    mma_gemm<3, 0, 0><<<GN, 256, GEMM_SMEM>>>(pX1, pG, pWh + 49152, pWl + 49152,
                                              rbias, pX2, nullptr, nullptr, NN);
    // o1 fused with final 128->2 projection: X2 -> partials
    mma_gemm<1, 1, 1><<<GN, 256, GEMM_SMEM>>>(pX2, nullptr, pWh + 98304, pWl + 98304,
                                              bo1, pX1, Wo2, pPart, NN);
    // reduce partials + bias -> out
    reduce_out_kernel<<<(NN * 2 + 255) / 256, 256>>>(pPart, bo2, out);
}